// round 1
// baseline (speedup 1.0000x reference)
#include <cuda_runtime.h>
#include <cstdint>
#include <cstddef>

// Problem constants (fixed by reference setup_inputs)
#define TT 2048      // tokens (B*L)
#define DM 1024      // d_model
#define ED 2048      // d_inner
#define NS 16        // d_state
#define NE 8         // experts
#define FF 2048      // mlp size
#define PROJW 96     // R + 2N = 64+16+16

// ---------------- scratch (device globals; no allocation) ----------------
__device__ float g_h1[TT * DM];
__device__ float g_xz[(size_t)TT * 2 * ED];   // 32MB  [T, 4096]  xm | z
__device__ float g_xc[(size_t)TT * ED];       // 16MB
__device__ float g_proj[TT * PROJW];          // [T,96]: dt(64) B(16) C(16)
__device__ float g_delta[(size_t)TT * ED];    // softplus(dt@W_dt + b)
__device__ float g_y[(size_t)TT * ED];        // scan output (gated)
__device__ float g_x1[TT * DM];               // x + mamba_out
__device__ float g_h2[TT * DM];               // rmsnorm2(x1)
__device__ int   g_cnt[NE];
__device__ int   g_tok[NE * TT];
__device__ int   g_slot[NE * TT];
__device__ float g_wtv[NE * TT];
__device__ float g_gu[(size_t)NE * TT * FF];  // 128MB: gate acts, then h=silu(g)*u
__device__ float g_ys[(size_t)2 * TT * DM];   // per-slot MoE outputs

// ---------------- small helpers ----------------
__device__ __forceinline__ float silu_f(float v) {
    return v / (1.f + __expf(-v));
}

// ---------------- zero counters ----------------
__global__ void zero_counts_kernel(int* cnt) {
    if (threadIdx.x < NE) cnt[threadIdx.x] = 0;
}

// ---------------- rmsnorm: one block per row of 1024 ----------------
__global__ void rmsnorm_kernel(const float* __restrict__ x,
                               const float* __restrict__ w,
                               float* __restrict__ o) {
    int t = blockIdx.x;
    const float4* xr = reinterpret_cast<const float4*>(x + (size_t)t * DM);
    float4 v = xr[threadIdx.x];                       // 256 threads * 4 = 1024
    float s = v.x * v.x + v.y * v.y + v.z * v.z + v.w * v.w;
    __shared__ float red[8];
    #pragma unroll
    for (int off = 16; off; off >>= 1) s += __shfl_xor_sync(0xffffffffu, s, off);
    int warp = threadIdx.x >> 5, lane = threadIdx.x & 31;
    if (lane == 0) red[warp] = s;
    __syncthreads();
    if (warp == 0) {
        float r = (lane < 8) ? red[lane] : 0.f;
        #pragma unroll
        for (int off = 4; off; off >>= 1) r += __shfl_xor_sync(0xffffffffu, r, off);
        if (lane == 0) red[0] = rsqrtf(r * (1.0f / DM) + 1e-6f);
    }
    __syncthreads();
    float rms = red[0];
    float4 wv = reinterpret_cast<const float4*>(w)[threadIdx.x];
    float4 ov = make_float4(v.x * rms * wv.x, v.y * rms * wv.y,
                            v.z * rms * wv.z, v.w * rms * wv.w);
    reinterpret_cast<float4*>(o + (size_t)t * DM)[threadIdx.x] = ov;
}

// ---------------- generic NT SGEMM: C[M,N] = A[M,K] @ B[N,K]^T ----------------
// EPI: 0 plain, 1 softplus(acc + bias[col]), 2 acc + extra[row*ldc+col]
template <int EPI>
__global__ __launch_bounds__(256, 2)
void sgemm_nt(const float* __restrict__ A, int lda,
              const float* __restrict__ Bw, int ldb,
              float* __restrict__ C, int ldc,
              int M, int N, int K,
              const float* __restrict__ bias,
              const float* __restrict__ extra) {
    __shared__ float As[8][128];
    __shared__ float Bs[8][128];
    const int tid = threadIdx.x;
    const int bm = blockIdx.y * 128, bn = blockIdx.x * 128;
    const int lr = tid >> 1;
    const int lc = (tid & 1) * 4;
    const int ty = tid >> 4, tx = tid & 15;
    float acc[8][8];
    #pragma unroll
    for (int i = 0; i < 8; i++)
        #pragma unroll
        for (int j = 0; j < 8; j++) acc[i][j] = 0.f;

    const bool avalid = (bm + lr) < M;
    const bool bvalid = (bn + lr) < N;
    const float* Aptr = A + (size_t)(bm + lr) * lda + lc;
    const float* Bptr = Bw + (size_t)(bn + lr) * ldb + lc;

    for (int k0 = 0; k0 < K; k0 += 8) {
        float4 av = avalid ? *reinterpret_cast<const float4*>(Aptr + k0)
                           : make_float4(0.f, 0.f, 0.f, 0.f);
        float4 bv = bvalid ? *reinterpret_cast<const float4*>(Bptr + k0)
                           : make_float4(0.f, 0.f, 0.f, 0.f);
        As[lc + 0][lr] = av.x; As[lc + 1][lr] = av.y;
        As[lc + 2][lr] = av.z; As[lc + 3][lr] = av.w;
        Bs[lc + 0][lr] = bv.x; Bs[lc + 1][lr] = bv.y;
        Bs[lc + 2][lr] = bv.z; Bs[lc + 3][lr] = bv.w;
        __syncthreads();
        #pragma unroll
        for (int kk = 0; kk < 8; kk++) {
            float af[8], bf[8];
            #pragma unroll
            for (int i = 0; i < 8; i++) af[i] = As[kk][ty * 8 + i];
            #pragma unroll
            for (int j = 0; j < 8; j++) bf[j] = Bs[kk][tx * 8 + j];
            #pragma unroll
            for (int i = 0; i < 8; i++)
                #pragma unroll
                for (int j = 0; j < 8; j++) acc[i][j] += af[i] * bf[j];
        }
        __syncthreads();
    }

    #pragma unroll
    for (int i = 0; i < 8; i++) {
        int row = bm + ty * 8 + i;
        if (row >= M) continue;
        #pragma unroll
        for (int j = 0; j < 8; j++) {
            int col = bn + tx * 8 + j;
            if (col >= N) continue;
            float v = acc[i][j];
            if (EPI == 1) {
                v += bias[col];
                v = (v > 20.f) ? v : log1pf(expf(v));   // softplus
            } else if (EPI == 2) {
                v += extra[(size_t)row * ldc + col];
            }
            C[(size_t)row * ldc + col] = v;
        }
    }
}

// ---------------- depthwise causal conv (K=4) + bias + silu ----------------
__global__ void conv_kernel(const float* __restrict__ xz,
                            const float* __restrict__ w,
                            const float* __restrict__ b,
                            float* __restrict__ xc) {
    int i = blockIdx.x * blockDim.x + threadIdx.x;
    if (i >= TT * ED) return;
    int t = i / ED, e = i - t * ED;
    float acc = b[e];
    #pragma unroll
    for (int k = 0; k < 4; k++) {
        int tt = t - 3 + k;
        if (tt >= 0) acc += w[e * 4 + k] * xz[(size_t)tt * (2 * ED) + e];
    }
    xc[i] = silu_f(acc);
}

// ---------------- selective scan: one thread per channel ----------------
__global__ void scan_kernel(const float* __restrict__ delta,
                            const float* __restrict__ xc,
                            const float* __restrict__ proj,
                            const float* __restrict__ xz,
                            const float* __restrict__ A_log,
                            const float* __restrict__ D_skip,
                            float* __restrict__ y) {
    int e = blockIdx.x * blockDim.x + threadIdx.x;
    if (e >= ED) return;
    float A[NS], h[NS];
    #pragma unroll
    for (int n = 0; n < NS; n++) {
        A[n] = -expf(A_log[e * NS + n]);
        h[n] = 0.f;
    }
    float Dk = D_skip[e];
    for (int t = 0; t < TT; t++) {
        float dlt = delta[(size_t)t * ED + e];
        float xv  = xc[(size_t)t * ED + e];
        const float4* Bp = reinterpret_cast<const float4*>(proj + (size_t)t * PROJW + 64);
        const float4* Cp = reinterpret_cast<const float4*>(proj + (size_t)t * PROJW + 80);
        float Bv[NS], Cv[NS];
        *reinterpret_cast<float4*>(&Bv[0])  = Bp[0];
        *reinterpret_cast<float4*>(&Bv[4])  = Bp[1];
        *reinterpret_cast<float4*>(&Bv[8])  = Bp[2];
        *reinterpret_cast<float4*>(&Bv[12]) = Bp[3];
        *reinterpret_cast<float4*>(&Cv[0])  = Cp[0];
        *reinterpret_cast<float4*>(&Cv[4])  = Cp[1];
        *reinterpret_cast<float4*>(&Cv[8])  = Cp[2];
        *reinterpret_cast<float4*>(&Cv[12]) = Cp[3];
        float dx = dlt * xv;
        float acc = 0.f;
        #pragma unroll
        for (int n = 0; n < NS; n++) {
            h[n] = __expf(dlt * A[n]) * h[n] + dx * Bv[n];
            acc += h[n] * Cv[n];
        }
        float zt = xz[(size_t)t * (2 * ED) + ED + e];
        y[(size_t)t * ED + e] = (acc + Dk * xv) * silu_f(zt);
    }
}

// ---------------- router: logits, softmax, top2, expert lists ----------------
__global__ void router_kernel(const float* __restrict__ h2,
                              const float* __restrict__ Wr,
                              float* __restrict__ logits_out,
                              int* __restrict__ cnt,
                              int* __restrict__ toks,
                              int* __restrict__ slots,
                              float* __restrict__ wts) {
    int t = blockIdx.x;
    int warp = threadIdx.x >> 5, lane = threadIdx.x & 31;
    __shared__ float sl[NE];
    const float* xr = h2 + (size_t)t * DM;
    const float* wr = Wr + (size_t)warp * DM;
    float acc = 0.f;
    for (int d = lane; d < DM; d += 32) acc += xr[d] * wr[d];
    #pragma unroll
    for (int off = 16; off; off >>= 1) acc += __shfl_xor_sync(0xffffffffu, acc, off);
    if (lane == 0) sl[warp] = acc;
    __syncthreads();
    if (threadIdx.x == 0) {
        float l[NE], mx = -1e30f;
        #pragma unroll
        for (int e = 0; e < NE; e++) {
            l[e] = sl[e];
            logits_out[(size_t)t * NE + e] = l[e];
            if (l[e] > mx) mx = l[e];
        }
        float p[NE], s = 0.f;
        #pragma unroll
        for (int e = 0; e < NE; e++) { p[e] = expf(l[e] - mx); s += p[e]; }
        float inv = 1.f / s;
        int i0 = 0; float b0 = -1.f;
        #pragma unroll
        for (int e = 0; e < NE; e++) if (p[e] > b0) { b0 = p[e]; i0 = e; }
        int i1 = -1; float b1 = -1.f;
        #pragma unroll
        for (int e = 0; e < NE; e++) if (e != i0 && p[e] > b1) { b1 = p[e]; i1 = e; }
        int p0 = atomicAdd(&cnt[i0], 1);
        toks[i0 * TT + p0] = t; slots[i0 * TT + p0] = 0; wts[i0 * TT + p0] = b0 * inv;
        int p1 = atomicAdd(&cnt[i1], 1);
        toks[i1 * TT + p1] = t; slots[i1 * TT + p1] = 1; wts[i1 * TT + p1] = b1 * inv;
    }
}

// ---------------- grouped MoE GEMM ----------------
// MODE 0: gate — gather A rows from h2 via token list;  C = acc  -> g_gu
// MODE 1: up   — gather;  C = silu(g_gu[o]) * acc  (in place into g_gu)
// MODE 2: down — A = g_gu entry rows;  scatter w*acc to slot buffer
template <int MODE>
__global__ __launch_bounds__(256, 2)
void moe_gemm(const float* __restrict__ Abase,
              const float* __restrict__ Wbase,
              float* __restrict__ Cbase,
              const int* __restrict__ counts,
              const int* __restrict__ toks,
              const int* __restrict__ slots,
              const float* __restrict__ wts) {
    const int e = blockIdx.z;
    const int cnt = counts[e];
    const int bm = blockIdx.y * 128;
    if (bm >= cnt) return;
    const int bn = blockIdx.x * 128;
    constexpr int K  = (MODE == 2) ? FF : DM;
    constexpr int NC = (MODE == 2) ? DM : FF;
    const float* Bw = Wbase + (size_t)e * K * NC;

    __shared__ float As[8][128];
    __shared__ float Bs[8][128];
    const int tid = threadIdx.x;
    const int lr = tid >> 1;
    const int lc = (tid & 1) * 4;
    const int ty = tid >> 4, tx = tid & 15;

    const int arow = bm + lr;
    const bool avalid = arow < cnt;
    const float* Aptr;
    if (MODE == 2) {
        Aptr = Abase + ((size_t)e * TT + arow) * FF + lc;
    } else {
        int tk = avalid ? toks[e * TT + arow] : 0;
        Aptr = Abase + (size_t)tk * DM + lc;
    }
    const bool bvalid = (bn + lr) < NC;
    const float* Bptr = Bw + (size_t)(bn + lr) * K + lc;

    float acc[8][8];
    #pragma unroll
    for (int i = 0; i < 8; i++)
        #pragma unroll
        for (int j = 0; j < 8; j++) acc[i][j] = 0.f;

    for (int k0 = 0; k0 < K; k0 += 8) {
        float4 av = avalid ? *reinterpret_cast<const float4*>(Aptr + k0)
                           : make_float4(0.f, 0.f, 0.f, 0.f);
        float4 bv = bvalid ? *reinterpret_cast<const float4*>(Bptr + k0)
                           : make_float4(0.f, 0.f, 0.f, 0.f);
        As[lc + 0][lr] = av.x; As[lc + 1][lr] = av.y;
        As[lc + 2][lr] = av.z; As[lc + 3][lr] = av.w;
        Bs[lc + 0][lr] = bv.x; Bs[lc + 1][lr] = bv.y;
        Bs[lc + 2][lr] = bv.z; Bs[lc + 3][lr] = bv.w;
        __syncthreads();
        #pragma unroll
        for (int kk = 0; kk < 8; kk++) {
            float af[8], bf[8];
            #pragma unroll
            for (int i = 0; i < 8; i++) af[i] = As[kk][ty * 8 + i];
            #pragma unroll
            for (int j = 0; j < 8; j++) bf[j] = Bs[kk][tx * 8 + j];
            #pragma unroll
            for (int i = 0; i < 8; i++)
                #pragma unroll
                for (int j = 0; j < 8; j++) acc[i][j] += af[i] * bf[j];
        }
        __syncthreads();
    }

    #pragma unroll
    for (int i = 0; i < 8; i++) {
        int r = bm + ty * 8 + i;
        if (r >= cnt) continue;
        #pragma unroll
        for (int j = 0; j < 8; j++) {
            int col = bn + tx * 8 + j;
            if (col >= NC) continue;
            if (MODE == 0) {
                Cbase[((size_t)e * TT + r) * FF + col] = acc[i][j];
            } else if (MODE == 1) {
                size_t o = ((size_t)e * TT + r) * FF + col;
                float g = Cbase[o];
                Cbase[o] = silu_f(g) * acc[i][j];
            } else {
                int tk = toks[e * TT + r];
                int s  = slots[e * TT + r];
                float w = wts[e * TT + r];
                Cbase[((size_t)s * TT + tk) * DM + col] = w * acc[i][j];
            }
        }
    }
}

// ---------------- final residual add ----------------
__global__ void final_add_kernel(const float* __restrict__ x1,
                                 const float* __restrict__ ys,
                                 float* __restrict__ out) {
    int i = blockIdx.x * blockDim.x + threadIdx.x;
    if (i >= TT * DM) return;
    out[i] = x1[i] + ys[i] + ys[(size_t)TT * DM + i];
}

// ---------------- host launch ----------------
extern "C" void kernel_launch(void* const* d_in, const int* in_sizes, int n_in,
                              void* d_out, int out_size) {
    const float* x        = (const float*)d_in[0];
    const float* rms1_w   = (const float*)d_in[1];
    const float* rms2_w   = (const float*)d_in[2];
    const float* W_in     = (const float*)d_in[3];
    const float* conv_w   = (const float*)d_in[4];
    const float* conv_b   = (const float*)d_in[5];
    const float* W_xproj  = (const float*)d_in[6];
    const float* W_dt     = (const float*)d_in[7];
    const float* b_dt     = (const float*)d_in[8];
    const float* A_log    = (const float*)d_in[9];
    const float* D_skip   = (const float*)d_in[10];
    const float* W_out    = (const float*)d_in[11];
    const float* W_router = (const float*)d_in[12];
    const float* gate_w   = (const float*)d_in[13];
    const float* up_w     = (const float*)d_in[14];
    const float* down_w   = (const float*)d_in[15];

    float* out        = (float*)d_out;
    float* out_logits = out + (size_t)TT * DM;

    float *h1, *xz, *xc, *proj, *delta, *y, *x1, *h2, *wtv, *gu, *ys;
    int *cnt, *tok, *slot;
    cudaGetSymbolAddress((void**)&h1, g_h1);
    cudaGetSymbolAddress((void**)&xz, g_xz);
    cudaGetSymbolAddress((void**)&xc, g_xc);
    cudaGetSymbolAddress((void**)&proj, g_proj);
    cudaGetSymbolAddress((void**)&delta, g_delta);
    cudaGetSymbolAddress((void**)&y, g_y);
    cudaGetSymbolAddress((void**)&x1, g_x1);
    cudaGetSymbolAddress((void**)&h2, g_h2);
    cudaGetSymbolAddress((void**)&cnt, g_cnt);
    cudaGetSymbolAddress((void**)&tok, g_tok);
    cudaGetSymbolAddress((void**)&slot, g_slot);
    cudaGetSymbolAddress((void**)&wtv, g_wtv);
    cudaGetSymbolAddress((void**)&gu, g_gu);
    cudaGetSymbolAddress((void**)&ys, g_ys);

    zero_counts_kernel<<<1, 32>>>(cnt);

    // h1 = rmsnorm(x)
    rmsnorm_kernel<<<TT, 256>>>(x, rms1_w, h1);

    // xz = h1 @ W_in^T   [2048, 4096]
    sgemm_nt<0><<<dim3(32, 16), 256>>>(h1, DM, W_in, DM, xz, 2 * ED,
                                       TT, 2 * ED, DM, nullptr, nullptr);

    // xc = silu(causal_conv(xm) + b)
    conv_kernel<<<(TT * ED) / 256, 256>>>(xz, conv_w, conv_b, xc);

    // proj = xc @ W_xproj^T   [2048, 96]
    sgemm_nt<0><<<dim3(1, 16), 256>>>(xc, ED, W_xproj, ED, proj, PROJW,
                                      TT, PROJW, ED, nullptr, nullptr);

    // delta = softplus(proj[:, :64] @ W_dt^T + b_dt)   [2048, 2048]
    sgemm_nt<1><<<dim3(16, 16), 256>>>(proj, PROJW, W_dt, 64, delta, ED,
                                       TT, ED, 64, b_dt, nullptr);

    // selective scan + D skip + silu(z) gating -> y
    scan_kernel<<<64, 32>>>(delta, xc, proj, xz, A_log, D_skip, y);

    // x1 = x + y @ W_out^T   [2048, 1024]
    sgemm_nt<2><<<dim3(8, 16), 256>>>(y, ED, W_out, ED, x1, DM,
                                      TT, DM, ED, nullptr, x);

    // h2 = rmsnorm(x1)
    rmsnorm_kernel<<<TT, 256>>>(x1, rms2_w, h2);

    // router: logits -> out tail; build expert lists
    router_kernel<<<TT, 256>>>(h2, W_router, out_logits, cnt, tok, slot, wtv);

    // grouped MoE
    moe_gemm<0><<<dim3(16, 16, NE), 256>>>(h2, gate_w, gu, cnt, tok, slot, wtv);
    moe_gemm<1><<<dim3(16, 16, NE), 256>>>(h2, up_w, gu, cnt, tok, slot, wtv);
    moe_gemm<2><<<dim3(8, 16, NE), 256>>>(gu, down_w, ys, cnt, tok, slot, wtv);

    // out = x1 + moe(slot0) + moe(slot1)
    final_add_kernel<<<(TT * DM) / 256, 256>>>(x1, ys, out);

    (void)in_sizes; (void)n_in; (void)out_size;
}

// round 4
// speedup vs baseline: 3.2966x; 3.2966x over previous
#include <cuda_runtime.h>
#include <cstdint>
#include <cstddef>
#include <math.h>

// Problem constants
#define TT 2048
#define DM 1024
#define ED 2048
#define NS 16
#define NE 8
#define FF 2048
#define PROJW 96
#define NCH 16
#define CHL 128   // TT / NCH

// ---------------- scratch (device globals; no allocation) ----------------
__device__ float g_h1[TT * DM];
__device__ float g_xz[(size_t)TT * 2 * ED];
__device__ float g_xc[(size_t)TT * ED];
__device__ float g_proj[TT * PROJW];
__device__ float g_delta[(size_t)TT * ED];
__device__ float g_y[(size_t)TT * ED];
__device__ float g_x1[TT * DM];
__device__ float g_h2[TT * DM];
__device__ int   g_cnt[NE];
__device__ int   g_tok[NE * TT];
__device__ int   g_slot[NE * TT];
__device__ float g_wtv[NE * TT];
__device__ float g_gu[(size_t)NE * TT * FF];
__device__ float g_ys[(size_t)2 * TT * DM];
__device__ float g_hl[(size_t)NCH * ED * NS];
__device__ float g_Pp[(size_t)NCH * ED * NS];
__device__ float g_cr[(size_t)NCH * ED * NS];

// ---------------- helpers ----------------
__device__ __forceinline__ uint32_t f2tf32(float f) {
    uint32_t u;
    asm("cvt.rna.tf32.f32 %0, %1;" : "=r"(u) : "f"(f));
    return u;
}
__device__ __forceinline__ float silu_f(float v) {
    return v / (1.f + __expf(-v));
}
__device__ __forceinline__ void mma16n8k8(float* d, const uint32_t* a, const uint32_t* b) {
    asm volatile(
        "mma.sync.aligned.m16n8k8.row.col.f32.tf32.tf32.f32 "
        "{%0,%1,%2,%3}, {%4,%5,%6,%7}, {%8,%9}, {%0,%1,%2,%3};"
        : "+f"(d[0]), "+f"(d[1]), "+f"(d[2]), "+f"(d[3])
        : "r"(a[0]), "r"(a[1]), "r"(a[2]), "r"(a[3]), "r"(b[0]), "r"(b[1]));
}

#define STR 20   // smem row stride in 4-byte words (pad 16 -> 20, conflict-free frags)

// ================= tensor-core tf32 GEMM:  C[M,N] = A[M,K] @ B[N,K]^T =================
// EPI: 0 plain, 1 softplus(acc + bias[col]), 2 acc + extra[row*ldc+col]
// Requires: M % 128 == 0, N % 8 == 0, K % 16 == 0, rows of A/B 16B-aligned.
template <int EPI>
__global__ __launch_bounds__(256)
void mma_gemm(const float* __restrict__ A, int lda,
              const float* __restrict__ Bw, int ldb,
              float* __restrict__ C, int ldc,
              int M, int N, int K,
              const float* __restrict__ bias,
              const float* __restrict__ extra) {
    __shared__ uint32_t sA[2][128 * STR];
    __shared__ uint32_t sB[2][128 * STR];
    const int tid = threadIdx.x;
    const int bm = blockIdx.y * 128, bn = blockIdx.x * 128;
    const int warp = tid >> 5, lane = tid & 31;
    const int g = lane >> 2, tig = lane & 3;
    const int wm = (warp & 3) * 32, wn = (warp >> 2) * 64;
    const int row0 = tid >> 2, c4 = (tid & 3) * 4;

    const float* aP0 = A + (size_t)(bm + row0) * lda + c4;
    const float* aP1 = aP0 + (size_t)64 * lda;
    const bool bv0 = (bn + row0) < N, bv1 = (bn + row0 + 64) < N;
    const float* bP0 = Bw + (size_t)(bn + row0) * ldb + c4;
    const float* bP1 = bP0 + (size_t)64 * ldb;

    const uint32_t so0 = row0 * STR + c4;
    const uint32_t so1 = (row0 + 64) * STR + c4;

    float acc[2][8][4];
    #pragma unroll
    for (int i = 0; i < 2; i++)
        #pragma unroll
        for (int j = 0; j < 8; j++)
            #pragma unroll
            for (int q = 0; q < 4; q++) acc[i][j][q] = 0.f;

    const int nk = K >> 4;

    {   // stage 0
        float4 a0 = *(const float4*)aP0;
        float4 a1 = *(const float4*)aP1;
        float4 b0 = bv0 ? *(const float4*)bP0 : make_float4(0.f, 0.f, 0.f, 0.f);
        float4 b1 = bv1 ? *(const float4*)bP1 : make_float4(0.f, 0.f, 0.f, 0.f);
        *(uint4*)&sA[0][so0] = make_uint4(f2tf32(a0.x), f2tf32(a0.y), f2tf32(a0.z), f2tf32(a0.w));
        *(uint4*)&sA[0][so1] = make_uint4(f2tf32(a1.x), f2tf32(a1.y), f2tf32(a1.z), f2tf32(a1.w));
        *(uint4*)&sB[0][so0] = make_uint4(f2tf32(b0.x), f2tf32(b0.y), f2tf32(b0.z), f2tf32(b0.w));
        *(uint4*)&sB[0][so1] = make_uint4(f2tf32(b1.x), f2tf32(b1.y), f2tf32(b1.z), f2tf32(b1.w));
    }
    __syncthreads();

    for (int kt = 0; kt < nk; kt++) {
        const int buf = kt & 1;
        float4 na0, na1, nb0, nb1;
        if (kt + 1 < nk) {
            int k0 = (kt + 1) << 4;
            na0 = *(const float4*)(aP0 + k0);
            na1 = *(const float4*)(aP1 + k0);
            nb0 = bv0 ? *(const float4*)(bP0 + k0) : make_float4(0.f, 0.f, 0.f, 0.f);
            nb1 = bv1 ? *(const float4*)(bP1 + k0) : make_float4(0.f, 0.f, 0.f, 0.f);
        }
        #pragma unroll
        for (int s = 0; s < 2; s++) {
            const int cb = s * 8;
            uint32_t af[2][4];
            #pragma unroll
            for (int mi = 0; mi < 2; mi++) {
                int rb = wm + mi * 16 + g;
                af[mi][0] = sA[buf][rb * STR + cb + tig];
                af[mi][1] = sA[buf][(rb + 8) * STR + cb + tig];
                af[mi][2] = sA[buf][rb * STR + cb + tig + 4];
                af[mi][3] = sA[buf][(rb + 8) * STR + cb + tig + 4];
            }
            #pragma unroll
            for (int j = 0; j < 8; j++) {
                uint32_t bf[2];
                int nr = wn + j * 8 + g;
                bf[0] = sB[buf][nr * STR + cb + tig];
                bf[1] = sB[buf][nr * STR + cb + tig + 4];
                mma16n8k8(acc[0][j], af[0], bf);
                mma16n8k8(acc[1][j], af[1], bf);
            }
        }
        if (kt + 1 < nk) {
            const int b2 = buf ^ 1;
            *(uint4*)&sA[b2][so0] = make_uint4(f2tf32(na0.x), f2tf32(na0.y), f2tf32(na0.z), f2tf32(na0.w));
            *(uint4*)&sA[b2][so1] = make_uint4(f2tf32(na1.x), f2tf32(na1.y), f2tf32(na1.z), f2tf32(na1.w));
            *(uint4*)&sB[b2][so0] = make_uint4(f2tf32(nb0.x), f2tf32(nb0.y), f2tf32(nb0.z), f2tf32(nb0.w));
            *(uint4*)&sB[b2][so1] = make_uint4(f2tf32(nb1.x), f2tf32(nb1.y), f2tf32(nb1.z), f2tf32(nb1.w));
        }
        __syncthreads();
    }

    // epilogue
    #pragma unroll
    for (int mi = 0; mi < 2; mi++) {
        #pragma unroll
        for (int j = 0; j < 8; j++) {
            int r0 = bm + wm + mi * 16 + g, r1 = r0 + 8;
            int c0 = bn + wn + j * 8 + 2 * tig;
            if (c0 >= N) continue;   // N multiple of 8; tile fully in or out
            float v00 = acc[mi][j][0], v01 = acc[mi][j][1];
            float v10 = acc[mi][j][2], v11 = acc[mi][j][3];
            if (EPI == 1) {
                float b0 = bias[c0], b1 = bias[c0 + 1];
                v00 += b0; v01 += b1; v10 += b0; v11 += b1;
                v00 = (v00 > 20.f) ? v00 : log1pf(expf(v00));
                v01 = (v01 > 20.f) ? v01 : log1pf(expf(v01));
                v10 = (v10 > 20.f) ? v10 : log1pf(expf(v10));
                v11 = (v11 > 20.f) ? v11 : log1pf(expf(v11));
            } else if (EPI == 2) {
                v00 += extra[(size_t)r0 * ldc + c0];
                v01 += extra[(size_t)r0 * ldc + c0 + 1];
                v10 += extra[(size_t)r1 * ldc + c0];
                v11 += extra[(size_t)r1 * ldc + c0 + 1];
            }
            *(float2*)&C[(size_t)r0 * ldc + c0] = make_float2(v00, v01);
            *(float2*)&C[(size_t)r1 * ldc + c0] = make_float2(v10, v11);
        }
    }
}

// ================= tensor-core tf32 grouped MoE GEMM =================
// MODE 0: gate (gather via toks -> gu); MODE 1: up (gather; gu = silu(gu)*acc);
// MODE 2: down (A = gu rows; scatter w*acc to slot buffer)
template <int MODE>
__global__ __launch_bounds__(256)
void mma_moe(const float* __restrict__ Ax,
             const float* __restrict__ Wbase,
             float* __restrict__ Cb,
             const int* __restrict__ counts,
             const int* __restrict__ toks,
             const int* __restrict__ slots,
             const float* __restrict__ wts) {
    constexpr int K  = (MODE == 2) ? FF : DM;
    constexpr int NC = (MODE == 2) ? DM : FF;
    const int e = blockIdx.z;
    const int cnt = counts[e];
    const int bm = blockIdx.y * 128;
    if (bm >= cnt) return;
    const int bn = blockIdx.x * 128;

    __shared__ uint32_t sA[2][128 * STR];
    __shared__ uint32_t sB[2][128 * STR];
    __shared__ int stok[128];

    const int tid = threadIdx.x;
    const int warp = tid >> 5, lane = tid & 31;
    const int g = lane >> 2, tig = lane & 3;
    const int wm = (warp & 3) * 32, wn = (warp >> 2) * 64;
    const int row0 = tid >> 2, c4 = (tid & 3) * 4;

    if (tid < 128) {
        int r = bm + tid;
        stok[tid] = (MODE == 2) ? 0 : ((r < cnt) ? toks[e * TT + r] : 0);
    }
    __syncthreads();

    const float* Bw = Wbase + (size_t)e * K * NC;
    const float* aP0;
    const float* aP1;
    if (MODE == 2) {
        aP0 = Ax + ((size_t)e * TT + bm + row0) * FF + c4;
        aP1 = aP0 + (size_t)64 * FF;
    } else {
        aP0 = Ax + (size_t)stok[row0] * DM + c4;
        aP1 = Ax + (size_t)stok[row0 + 64] * DM + c4;
    }
    const float* bP0 = Bw + (size_t)(bn + row0) * K + c4;
    const float* bP1 = bP0 + (size_t)64 * K;

    const uint32_t so0 = row0 * STR + c4;
    const uint32_t so1 = (row0 + 64) * STR + c4;

    float acc[2][8][4];
    #pragma unroll
    for (int i = 0; i < 2; i++)
        #pragma unroll
        for (int j = 0; j < 8; j++)
            #pragma unroll
            for (int q = 0; q < 4; q++) acc[i][j][q] = 0.f;

    const int nk = K >> 4;

    {
        float4 a0 = *(const float4*)aP0;
        float4 a1 = *(const float4*)aP1;
        float4 b0 = *(const float4*)bP0;
        float4 b1 = *(const float4*)bP1;
        *(uint4*)&sA[0][so0] = make_uint4(f2tf32(a0.x), f2tf32(a0.y), f2tf32(a0.z), f2tf32(a0.w));
        *(uint4*)&sA[0][so1] = make_uint4(f2tf32(a1.x), f2tf32(a1.y), f2tf32(a1.z), f2tf32(a1.w));
        *(uint4*)&sB[0][so0] = make_uint4(f2tf32(b0.x), f2tf32(b0.y), f2tf32(b0.z), f2tf32(b0.w));
        *(uint4*)&sB[0][so1] = make_uint4(f2tf32(b1.x), f2tf32(b1.y), f2tf32(b1.z), f2tf32(b1.w));
    }
    __syncthreads();

    for (int kt = 0; kt < nk; kt++) {
        const int buf = kt & 1;
        float4 na0, na1, nb0, nb1;
        if (kt + 1 < nk) {
            int k0 = (kt + 1) << 4;
            na0 = *(const float4*)(aP0 + k0);
            na1 = *(const float4*)(aP1 + k0);
            nb0 = *(const float4*)(bP0 + k0);
            nb1 = *(const float4*)(bP1 + k0);
        }
        #pragma unroll
        for (int s = 0; s < 2; s++) {
            const int cb = s * 8;
            uint32_t af[2][4];
            #pragma unroll
            for (int mi = 0; mi < 2; mi++) {
                int rb = wm + mi * 16 + g;
                af[mi][0] = sA[buf][rb * STR + cb + tig];
                af[mi][1] = sA[buf][(rb + 8) * STR + cb + tig];
                af[mi][2] = sA[buf][rb * STR + cb + tig + 4];
                af[mi][3] = sA[buf][(rb + 8) * STR + cb + tig + 4];
            }
            #pragma unroll
            for (int j = 0; j < 8; j++) {
                uint32_t bf[2];
                int nr = wn + j * 8 + g;
                bf[0] = sB[buf][nr * STR + cb + tig];
                bf[1] = sB[buf][nr * STR + cb + tig + 4];
                mma16n8k8(acc[0][j], af[0], bf);
                mma16n8k8(acc[1][j], af[1], bf);
            }
        }
        if (kt + 1 < nk) {
            const int b2 = buf ^ 1;
            *(uint4*)&sA[b2][so0] = make_uint4(f2tf32(na0.x), f2tf32(na0.y), f2tf32(na0.z), f2tf32(na0.w));
            *(uint4*)&sA[b2][so1] = make_uint4(f2tf32(na1.x), f2tf32(na1.y), f2tf32(na1.z), f2tf32(na1.w));
            *(uint4*)&sB[b2][so0] = make_uint4(f2tf32(nb0.x), f2tf32(nb0.y), f2tf32(nb0.z), f2tf32(nb0.w));
            *(uint4*)&sB[b2][so1] = make_uint4(f2tf32(nb1.x), f2tf32(nb1.y), f2tf32(nb1.z), f2tf32(nb1.w));
        }
        __syncthreads();
    }

    // epilogue
    #pragma unroll
    for (int mi = 0; mi < 2; mi++) {
        int rl0 = wm + mi * 16 + g;           // local rows
        int r0 = bm + rl0, r1 = r0 + 8;
        bool rv0 = r0 < cnt, rv1 = r1 < cnt;
        int tk0 = 0, sl0 = 0, tk1 = 0, sl1 = 0;
        float w0 = 0.f, w1 = 0.f;
        if (MODE == 2) {
            if (rv0) { tk0 = toks[e * TT + r0]; sl0 = slots[e * TT + r0]; w0 = wts[e * TT + r0]; }
            if (rv1) { tk1 = toks[e * TT + r1]; sl1 = slots[e * TT + r1]; w1 = wts[e * TT + r1]; }
        }
        #pragma unroll
        for (int j = 0; j < 8; j++) {
            int c0 = bn + wn + j * 8 + 2 * tig;
            float v00 = acc[mi][j][0], v01 = acc[mi][j][1];
            float v10 = acc[mi][j][2], v11 = acc[mi][j][3];
            if (MODE == 0) {
                if (rv0) *(float2*)&Cb[((size_t)e * TT + r0) * FF + c0] = make_float2(v00, v01);
                if (rv1) *(float2*)&Cb[((size_t)e * TT + r1) * FF + c0] = make_float2(v10, v11);
            } else if (MODE == 1) {
                if (rv0) {
                    size_t o = ((size_t)e * TT + r0) * FF + c0;
                    float2 gv = *(float2*)&Cb[o];
                    *(float2*)&Cb[o] = make_float2(silu_f(gv.x) * v00, silu_f(gv.y) * v01);
                }
                if (rv1) {
                    size_t o = ((size_t)e * TT + r1) * FF + c0;
                    float2 gv = *(float2*)&Cb[o];
                    *(float2*)&Cb[o] = make_float2(silu_f(gv.x) * v10, silu_f(gv.y) * v11);
                }
            } else {
                if (rv0) *(float2*)&Cb[((size_t)sl0 * TT + tk0) * DM + c0] = make_float2(w0 * v00, w0 * v01);
                if (rv1) *(float2*)&Cb[((size_t)sl1 * TT + tk1) * DM + c0] = make_float2(w1 * v10, w1 * v11);
            }
        }
    }
}

// ---------------- misc kernels ----------------
__global__ void zero_counts_kernel(int* cnt) {
    if (threadIdx.x < NE) cnt[threadIdx.x] = 0;
}

__global__ void rmsnorm_kernel(const float* __restrict__ x,
                               const float* __restrict__ w,
                               float* __restrict__ o) {
    int t = blockIdx.x;
    const float4* xr = reinterpret_cast<const float4*>(x + (size_t)t * DM);
    float4 v = xr[threadIdx.x];
    float s = v.x * v.x + v.y * v.y + v.z * v.z + v.w * v.w;
    __shared__ float red[8];
    #pragma unroll
    for (int off = 16; off; off >>= 1) s += __shfl_xor_sync(0xffffffffu, s, off);
    int warp = threadIdx.x >> 5, lane = threadIdx.x & 31;
    if (lane == 0) red[warp] = s;
    __syncthreads();
    if (warp == 0) {
        float r = (lane < 8) ? red[lane] : 0.f;
        #pragma unroll
        for (int off = 4; off; off >>= 1) r += __shfl_xor_sync(0xffffffffu, r, off);
        if (lane == 0) red[0] = rsqrtf(r * (1.0f / DM) + 1e-6f);
    }
    __syncthreads();
    float rms = red[0];
    float4 wv = reinterpret_cast<const float4*>(w)[threadIdx.x];
    reinterpret_cast<float4*>(o + (size_t)t * DM)[threadIdx.x] =
        make_float4(v.x * rms * wv.x, v.y * rms * wv.y, v.z * rms * wv.z, v.w * rms * wv.w);
}

__global__ void conv_kernel(const float* __restrict__ xz,
                            const float* __restrict__ w,
                            const float* __restrict__ b,
                            float* __restrict__ xc) {
    int i = blockIdx.x * blockDim.x + threadIdx.x;
    if (i >= TT * ED) return;
    int t = i / ED, e = i - t * ED;
    float acc = b[e];
    #pragma unroll
    for (int k = 0; k < 4; k++) {
        int tt = t - 3 + k;
        if (tt >= 0) acc += w[e * 4 + k] * xz[(size_t)tt * (2 * ED) + e];
    }
    xc[i] = silu_f(acc);
}

// ---------------- chunked selective scan ----------------
__global__ void scan_pass1(const float* __restrict__ delta,
                           const float* __restrict__ xc,
                           const float* __restrict__ proj,
                           const float* __restrict__ xz,
                           const float* __restrict__ A_log,
                           const float* __restrict__ D_skip,
                           float* __restrict__ y,
                           float* __restrict__ hl,
                           float* __restrict__ Pp) {
    int e = blockIdx.x * 128 + threadIdx.x;
    int c = blockIdx.y;
    float A[NS], h[NS], P[NS];
    #pragma unroll
    for (int n = 0; n < NS; n++) {
        A[n] = -expf(A_log[e * NS + n]);
        h[n] = 0.f;
        P[n] = 1.f;
    }
    float Dk = D_skip[e];
    int t0 = c * CHL;
    for (int tt = 0; tt < CHL; tt++) {
        int t = t0 + tt;
        float dlt = delta[(size_t)t * ED + e];
        float xv  = xc[(size_t)t * ED + e];
        const float4* Bp = reinterpret_cast<const float4*>(proj + (size_t)t * PROJW + 64);
        const float4* Cp = reinterpret_cast<const float4*>(proj + (size_t)t * PROJW + 80);
        float Bv[NS], Cv[NS];
        *reinterpret_cast<float4*>(&Bv[0])  = Bp[0];
        *reinterpret_cast<float4*>(&Bv[4])  = Bp[1];
        *reinterpret_cast<float4*>(&Bv[8])  = Bp[2];
        *reinterpret_cast<float4*>(&Bv[12]) = Bp[3];
        *reinterpret_cast<float4*>(&Cv[0])  = Cp[0];
        *reinterpret_cast<float4*>(&Cv[4])  = Cp[1];
        *reinterpret_cast<float4*>(&Cv[8])  = Cp[2];
        *reinterpret_cast<float4*>(&Cv[12]) = Cp[3];
        float dx = dlt * xv;
        float acc = 0.f;
        #pragma unroll
        for (int n = 0; n < NS; n++) {
            float r = __expf(dlt * A[n]);
            h[n] = r * h[n] + dx * Bv[n];
            acc += h[n] * Cv[n];
            P[n] *= r;
        }
        float zt = xz[(size_t)t * (2 * ED) + ED + e];
        y[(size_t)t * ED + e] = (acc + Dk * xv) * silu_f(zt);
    }
    size_t base = ((size_t)c * ED + e) * NS;
    #pragma unroll
    for (int q = 0; q < 4; q++) {
        reinterpret_cast<float4*>(hl + base)[q] = *reinterpret_cast<float4*>(&h[q * 4]);
        reinterpret_cast<float4*>(Pp + base)[q] = *reinterpret_cast<float4*>(&P[q * 4]);
    }
}

__global__ void scan_carry(const float* __restrict__ hl,
                           const float* __restrict__ Pp,
                           float* __restrict__ cr) {
    int e = blockIdx.x * 256 + threadIdx.x;
    float carry[NS];
    #pragma unroll
    for (int n = 0; n < NS; n++) carry[n] = 0.f;
    for (int c = 0; c < NCH; c++) {
        size_t b = ((size_t)c * ED + e) * NS;
        #pragma unroll
        for (int n = 0; n < NS; n++) cr[b + n] = carry[n];
        #pragma unroll
        for (int n = 0; n < NS; n++) carry[n] = hl[b + n] + Pp[b + n] * carry[n];
    }
}

__global__ void scan_pass2(const float* __restrict__ delta,
                           const float* __restrict__ proj,
                           const float* __restrict__ xz,
                           const float* __restrict__ A_log,
                           const float* __restrict__ cr,
                           float* __restrict__ y) {
    int e = blockIdx.x * 128 + threadIdx.x;
    int c = blockIdx.y + 1;
    float A[NS], q[NS];
    size_t base = ((size_t)c * ED + e) * NS;
    #pragma unroll
    for (int n = 0; n < NS; n++) {
        A[n] = -expf(A_log[e * NS + n]);
        q[n] = cr[base + n];
    }
    int t0 = c * CHL;
    for (int tt = 0; tt < CHL; tt++) {
        int t = t0 + tt;
        float dlt = delta[(size_t)t * ED + e];
        const float4* Cp = reinterpret_cast<const float4*>(proj + (size_t)t * PROJW + 80);
        float Cv[NS];
        *reinterpret_cast<float4*>(&Cv[0])  = Cp[0];
        *reinterpret_cast<float4*>(&Cv[4])  = Cp[1];
        *reinterpret_cast<float4*>(&Cv[8])  = Cp[2];
        *reinterpret_cast<float4*>(&Cv[12]) = Cp[3];
        float acc = 0.f;
        #pragma unroll
        for (int n = 0; n < NS; n++) {
            q[n] *= __expf(dlt * A[n]);
            acc += Cv[n] * q[n];
        }
        float zt = xz[(size_t)t * (2 * ED) + ED + e];
        y[(size_t)t * ED + e] += acc * silu_f(zt);
    }
}

// ---------------- router ----------------
__global__ void router_kernel(const float* __restrict__ h2,
                              const float* __restrict__ Wr,
                              float* __restrict__ logits_out,
                              int* __restrict__ cnt,
                              int* __restrict__ toks,
                              int* __restrict__ slots,
                              float* __restrict__ wts) {
    int t = blockIdx.x;
    int warp = threadIdx.x >> 5, lane = threadIdx.x & 31;
    __shared__ float sl[NE];
    const float* xr = h2 + (size_t)t * DM;
    const float* wr = Wr + (size_t)warp * DM;
    float acc = 0.f;
    for (int d = lane; d < DM; d += 32) acc += xr[d] * wr[d];
    #pragma unroll
    for (int off = 16; off; off >>= 1) acc += __shfl_xor_sync(0xffffffffu, acc, off);
    if (lane == 0) sl[warp] = acc;
    __syncthreads();
    if (threadIdx.x == 0) {
        float l[NE], mx = -1e30f;
        #pragma unroll
        for (int e = 0; e < NE; e++) {
            l[e] = sl[e];
            logits_out[(size_t)t * NE + e] = l[e];
            if (l[e] > mx) mx = l[e];
        }
        float p[NE], s = 0.f;
        #pragma unroll
        for (int e = 0; e < NE; e++) { p[e] = expf(l[e] - mx); s += p[e]; }
        float inv = 1.f / s;
        int i0 = 0; float b0 = -1.f;
        #pragma unroll
        for (int e = 0; e < NE; e++) if (p[e] > b0) { b0 = p[e]; i0 = e; }
        int i1 = -1; float b1 = -1.f;
        #pragma unroll
        for (int e = 0; e < NE; e++) if (e != i0 && p[e] > b1) { b1 = p[e]; i1 = e; }
        int p0 = atomicAdd(&cnt[i0], 1);
        toks[i0 * TT + p0] = t; slots[i0 * TT + p0] = 0; wts[i0 * TT + p0] = b0 * inv;
        int p1 = atomicAdd(&cnt[i1], 1);
        toks[i1 * TT + p1] = t; slots[i1 * TT + p1] = 1; wts[i1 * TT + p1] = b1 * inv;
    }
}

__global__ void final_add_kernel(const float* __restrict__ x1,
                                 const float* __restrict__ ys,
                                 float* __restrict__ out) {
    int i = blockIdx.x * blockDim.x + threadIdx.x;
    if (i >= TT * DM) return;
    out[i] = x1[i] + ys[i] + ys[(size_t)TT * DM + i];
}

// ---------------- host launch ----------------
extern "C" void kernel_launch(void* const* d_in, const int* in_sizes, int n_in,
                              void* d_out, int out_size) {
    const float* x        = (const float*)d_in[0];
    const float* rms1_w   = (const float*)d_in[1];
    const float* rms2_w   = (const float*)d_in[2];
    const float* W_in     = (const float*)d_in[3];
    const float* conv_w   = (const float*)d_in[4];
    const float* conv_b   = (const float*)d_in[5];
    const float* W_xproj  = (const float*)d_in[6];
    const float* W_dt     = (const float*)d_in[7];
    const float* b_dt     = (const float*)d_in[8];
    const float* A_log    = (const float*)d_in[9];
    const float* D_skip   = (const float*)d_in[10];
    const float* W_out    = (const float*)d_in[11];
    const float* W_router = (const float*)d_in[12];
    const float* gate_w   = (const float*)d_in[13];
    const float* up_w     = (const float*)d_in[14];
    const float* down_w   = (const float*)d_in[15];

    float* out        = (float*)d_out;
    float* out_logits = out + (size_t)TT * DM;

    float *h1, *xz, *xc, *proj, *delta, *y, *x1, *h2, *wtv, *gu, *ys, *hl, *Pp, *cr;
    int *cnt, *tok, *slot;
    cudaGetSymbolAddress((void**)&h1, g_h1);
    cudaGetSymbolAddress((void**)&xz, g_xz);
    cudaGetSymbolAddress((void**)&xc, g_xc);
    cudaGetSymbolAddress((void**)&proj, g_proj);
    cudaGetSymbolAddress((void**)&delta, g_delta);
    cudaGetSymbolAddress((void**)&y, g_y);
    cudaGetSymbolAddress((void**)&x1, g_x1);
    cudaGetSymbolAddress((void**)&h2, g_h2);
    cudaGetSymbolAddress((void**)&cnt, g_cnt);
    cudaGetSymbolAddress((void**)&tok, g_tok);
    cudaGetSymbolAddress((void**)&slot, g_slot);
    cudaGetSymbolAddress((void**)&wtv, g_wtv);
    cudaGetSymbolAddress((void**)&gu, g_gu);
    cudaGetSymbolAddress((void**)&ys, g_ys);
    cudaGetSymbolAddress((void**)&hl, g_hl);
    cudaGetSymbolAddress((void**)&Pp, g_Pp);
    cudaGetSymbolAddress((void**)&cr, g_cr);

    zero_counts_kernel<<<1, 32>>>(cnt);
    rmsnorm_kernel<<<TT, 256>>>(x, rms1_w, h1);

    // xz = h1 @ W_in^T   [2048, 4096]
    mma_gemm<0><<<dim3(32, 16), 256>>>(h1, DM, W_in, DM, xz, 2 * ED,
                                       TT, 2 * ED, DM, nullptr, nullptr);
    conv_kernel<<<(TT * ED) / 256, 256>>>(xz, conv_w, conv_b, xc);

    // proj = xc @ W_xproj^T   [2048, 96]
    mma_gemm<0><<<dim3(1, 16), 256>>>(xc, ED, W_xproj, ED, proj, PROJW,
                                      TT, PROJW, ED, nullptr, nullptr);

    // delta = softplus(proj[:, :64] @ W_dt^T + b_dt)   [2048, 2048]
    mma_gemm<1><<<dim3(16, 16), 256>>>(proj, PROJW, W_dt, 64, delta, ED,
                                       TT, ED, 64, b_dt, nullptr);

    // chunked selective scan
    scan_pass1<<<dim3(ED / 128, NCH), 128>>>(delta, xc, proj, xz, A_log, D_skip, y, hl, Pp);
    scan_carry<<<ED / 256, 256>>>(hl, Pp, cr);
    scan_pass2<<<dim3(ED / 128, NCH - 1), 128>>>(delta, proj, xz, A_log, cr, y);

    // x1 = x + y @ W_out^T
    mma_gemm<2><<<dim3(8, 16), 256>>>(y, ED, W_out, ED, x1, DM,
                                      TT, DM, ED, nullptr, x);

    rmsnorm_kernel<<<TT, 256>>>(x1, rms2_w, h2);
    router_kernel<<<TT, 256>>>(h2, W_router, out_logits, cnt, tok, slot, wtv);

    mma_moe<0><<<dim3(16, 16, NE), 256>>>(h2, gate_w, gu, cnt, tok, slot, wtv);
    mma_moe<1><<<dim3(16, 16, NE), 256>>>(h2, up_w, gu, cnt, tok, slot, wtv);
    mma_moe<2><<<dim3(8, 16, NE), 256>>>(gu, down_w, ys, cnt, tok, slot, wtv);

    final_add_kernel<<<(TT * DM) / 256, 256>>>(x1, ys, out);

    (void)in_sizes; (void)n_in; (void)out_size;
}